// round 4
// baseline (speedup 1.0000x reference)
#include <cuda_runtime.h>

// ---------------------------------------------------------------------------
// EdgeAttrConstruct: out[e] = L(L(L((x[s]+x[d])@W0+b0)@W1+b1)@W2+b2), L=leaky(0.05)
// Factored: h0 = x@W0 per node (50k rows);  per edge: act1 = L(h0[s]+h0[d]+b0)
// then two TF32 tensor-core GEMMs per 64-edge tile with weights resident in smem.
// NOTE: edge_index is int32 (JAX canonicalizes int64->int32 with x64 disabled).
// ---------------------------------------------------------------------------

#define SLOPE 0.05f

constexpr int ND = 64;    // node dim
constexpr int HD = 128;   // hidden dim
constexpr int OD = 64;    // out dim
constexpr int MAX_NODES = 50000;

constexpr int TILE_E = 64;          // edges per tile
constexpr int S1 = 136;             // smem stride for 128-wide rows (==8 mod 32: conflict-free frag loads)
constexpr int S2 = 72;              // smem stride for W2 (64-wide)
constexpr int NW1 = HD * S1;        // 17408 floats
constexpr int NW2 = HD * S2;        //  9216 floats
constexpr int NACT = TILE_E * S1;   //  8704 floats
constexpr int SMEM_FLOATS = NW1 + NW2 + 2 * NACT + 128 + 128 + 64;
constexpr int SMEM_BYTES = SMEM_FLOATS * 4;   // 177408 B

__device__ float g_h0[(size_t)MAX_NODES * HD];   // node-precomputed x@W0 (fp32)

__device__ __forceinline__ float leaky(float v) { return v >= 0.f ? v : SLOPE * v; }

__device__ __forceinline__ unsigned tf32u(float x) {
    unsigned u;
    asm("cvt.rna.tf32.f32 %0, %1;" : "=r"(u) : "f"(x));
    return u;
}
__device__ __forceinline__ float tf32f(float x) { return __uint_as_float(tf32u(x)); }

__device__ __forceinline__ void mma_tf32(float* c, const unsigned* a, const unsigned* b) {
    asm volatile(
        "mma.sync.aligned.m16n8k8.row.col.f32.tf32.tf32.f32 "
        "{%0,%1,%2,%3}, {%4,%5,%6,%7}, {%8,%9}, {%0,%1,%2,%3};"
        : "+f"(c[0]), "+f"(c[1]), "+f"(c[2]), "+f"(c[3])
        : "r"(a[0]), "r"(a[1]), "r"(a[2]), "r"(a[3]), "r"(b[0]), "r"(b[1]));
}

// ---------------------------------------------------------------------------
// Kernel 1: g_h0[n] = x[n] @ W0   (50000x64 @ 64x128), fp32 FFMA, smem-tiled.
// Block: 256 threads, 64 nodes. Each thread: 8 nodes x 4 cols.
// ---------------------------------------------------------------------------
__global__ __launch_bounds__(256) void node_gemm(
    const float* __restrict__ x, const float* __restrict__ W0, int n_nodes)
{
    __shared__ float sW[ND * HD];    // W0[k][j], 32 KB
    __shared__ float sX[64 * 68];    // x tile, padded stride 68

    const int tid = threadIdx.x;
    for (int i = tid; i < ND * HD; i += 256) sW[i] = W0[i];

    const int node0 = blockIdx.x * 64;
    for (int t = tid; t < 64 * 16; t += 256) {   // float4 units
        int r = t >> 4, q = t & 15;
        int node = node0 + r;
        float4 v = make_float4(0.f, 0.f, 0.f, 0.f);
        if (node < n_nodes) v = *reinterpret_cast<const float4*>(x + (size_t)node * ND + q * 4);
        *reinterpret_cast<float4*>(sX + r * 68 + q * 4) = v;
    }
    __syncthreads();

    const int tx = tid & 31, ty = tid >> 5;
    float acc[8][4];
#pragma unroll
    for (int i = 0; i < 8; i++)
#pragma unroll
        for (int j = 0; j < 4; j++) acc[i][j] = 0.f;

#pragma unroll 4
    for (int k = 0; k < ND; k++) {
        float w[4];
#pragma unroll
        for (int j = 0; j < 4; j++) w[j] = sW[k * HD + tx + 32 * j];
#pragma unroll
        for (int i = 0; i < 8; i++) {
            float xv = sX[(ty + 8 * i) * 68 + k];
#pragma unroll
            for (int j = 0; j < 4; j++) acc[i][j] = fmaf(xv, w[j], acc[i][j]);
        }
    }

#pragma unroll
    for (int i = 0; i < 8; i++) {
        int node = node0 + ty + 8 * i;
        if (node < n_nodes) {
#pragma unroll
            for (int j = 0; j < 4; j++)
                g_h0[(size_t)node * HD + tx + 32 * j] = acc[i][j];
        }
    }
}

// ---------------------------------------------------------------------------
// Kernel 2: persistent edge MLP. grid = 148, 256 threads, 177 KB dyn smem.
// Per 64-edge tile:
//   gather:  sA1[e][k] = tf32(leaky(h0[src]+h0[dst]+b0))
//   GEMM1:   sA2 = tf32(leaky(sA1 @ W1 + b1))      (64x128 @ 128x128)
//   GEMM2:   out = leaky(sA2 @ W2 + b2)            (64x64  @ 128x64)  -> gmem
// ---------------------------------------------------------------------------
__global__ __launch_bounds__(256) void edge_mlp(
    const int* __restrict__ ei,
    const float* __restrict__ W1, const float* __restrict__ W2,
    const float* __restrict__ b0, const float* __restrict__ b1,
    const float* __restrict__ b2,
    float* __restrict__ out, int n_edges, int n_nodes)
{
    extern __shared__ float sm[];
    float* sW1 = sm;                 // [128][136] tf32-rounded
    float* sW2 = sW1 + NW1;          // [128][72]  tf32-rounded
    float* sA1 = sW2 + NW2;          // [64][136]
    float* sA2 = sA1 + NACT;         // [64][136]
    float* sB0 = sA2 + NACT;         // [128]
    float* sB1 = sB0 + 128;          // [128]
    float* sB2 = sB1 + 128;          // [64]

    const int tid = threadIdx.x;

    // one-time weight staging (tf32-rounded once here = same as cvt per mma)
    for (int i = tid; i < HD * HD; i += 256)
        sW1[(i >> 7) * S1 + (i & 127)] = tf32f(W1[i]);
    for (int i = tid; i < HD * OD; i += 256)
        sW2[(i >> 6) * S2 + (i & 63)] = tf32f(W2[i]);
    if (tid < 128) { sB0[tid] = b0[tid]; sB1[tid] = b1[tid]; }
    if (tid < 64)  sB2[tid] = b2[tid];
    __syncthreads();

    const int lane = tid & 31, wid = tid >> 5;
    const int g = lane >> 2, c = lane & 3;
    // GEMM1 warp tile: 32 (m) x 32 (n);  GEMM2 warp tile: 32 (m) x 16 (n)
    const int m0  = (wid & 1) * 32;
    const int n0  = (wid >> 1) * 32;
    const int n02 = (wid >> 1) * 16;

    const int n_tiles = (n_edges + TILE_E - 1) / TILE_E;
    for (int tile = blockIdx.x; tile < n_tiles; tile += gridDim.x) {
        const int e0 = tile * TILE_E;

        // ---- gather + layer-0 bias/activation ----
        for (int t = tid; t < TILE_E * 32; t += 256) {   // 32 float4 per edge
            int e = t >> 5, q = t & 31;
            float4 w;
            if (e0 + e < n_edges) {
                int s = __ldg(ei + e0 + e);
                int d = __ldg(ei + n_edges + e0 + e);
                s = min(max(s, 0), n_nodes - 1);   // defensive clamp (branchless)
                d = min(max(d, 0), n_nodes - 1);
                float4 va = *reinterpret_cast<const float4*>(&g_h0[(size_t)s * HD + q * 4]);
                float4 vb = *reinterpret_cast<const float4*>(&g_h0[(size_t)d * HD + q * 4]);
                float4 bb = *reinterpret_cast<const float4*>(sB0 + q * 4);
                w.x = tf32f(leaky(va.x + vb.x + bb.x));
                w.y = tf32f(leaky(va.y + vb.y + bb.y));
                w.z = tf32f(leaky(va.z + vb.z + bb.z));
                w.w = tf32f(leaky(va.w + vb.w + bb.w));
            } else {
                w = make_float4(0.f, 0.f, 0.f, 0.f);
            }
            *reinterpret_cast<float4*>(sA1 + e * S1 + q * 4) = w;
        }
        __syncthreads();

        // ---- GEMM1: sA2 = leaky(sA1 @ W1 + b1) ----
        {
            float acc[2][4][4];
#pragma unroll
            for (int i = 0; i < 2; i++)
#pragma unroll
                for (int j = 0; j < 4; j++)
#pragma unroll
                    for (int r = 0; r < 4; r++) acc[i][j][r] = 0.f;

#pragma unroll
            for (int k0 = 0; k0 < HD; k0 += 8) {
                unsigned a[2][4];
#pragma unroll
                for (int i = 0; i < 2; i++) {
                    const float* Ab = sA1 + (m0 + i * 16) * S1 + k0;
                    a[i][0] = __float_as_uint(Ab[g * S1 + c]);
                    a[i][1] = __float_as_uint(Ab[(g + 8) * S1 + c]);
                    a[i][2] = __float_as_uint(Ab[g * S1 + c + 4]);
                    a[i][3] = __float_as_uint(Ab[(g + 8) * S1 + c + 4]);
                }
                unsigned bf[4][2];
#pragma unroll
                for (int j = 0; j < 4; j++) {
                    const float* Bb = sW1 + (k0 + c) * S1 + n0 + j * 8 + g;
                    bf[j][0] = __float_as_uint(Bb[0]);
                    bf[j][1] = __float_as_uint(Bb[4 * S1]);
                }
#pragma unroll
                for (int i = 0; i < 2; i++)
#pragma unroll
                    for (int j = 0; j < 4; j++) mma_tf32(acc[i][j], a[i], bf[j]);
            }

#pragma unroll
            for (int i = 0; i < 2; i++)
#pragma unroll
                for (int j = 0; j < 4; j++) {
                    int row = m0 + i * 16 + g;
                    int col = n0 + j * 8 + 2 * c;
                    float2 v0, v1;
                    v0.x = tf32f(leaky(acc[i][j][0] + sB1[col]));
                    v0.y = tf32f(leaky(acc[i][j][1] + sB1[col + 1]));
                    v1.x = tf32f(leaky(acc[i][j][2] + sB1[col]));
                    v1.y = tf32f(leaky(acc[i][j][3] + sB1[col + 1]));
                    *reinterpret_cast<float2*>(sA2 + row * S1 + col) = v0;
                    *reinterpret_cast<float2*>(sA2 + (row + 8) * S1 + col) = v1;
                }
        }
        __syncthreads();

        // ---- GEMM2: out = leaky(sA2 @ W2 + b2) ----
        {
            float acc[2][2][4];
#pragma unroll
            for (int i = 0; i < 2; i++)
#pragma unroll
                for (int j = 0; j < 2; j++)
#pragma unroll
                    for (int r = 0; r < 4; r++) acc[i][j][r] = 0.f;

#pragma unroll
            for (int k0 = 0; k0 < HD; k0 += 8) {
                unsigned a[2][4];
#pragma unroll
                for (int i = 0; i < 2; i++) {
                    const float* Ab = sA2 + (m0 + i * 16) * S1 + k0;
                    a[i][0] = __float_as_uint(Ab[g * S1 + c]);
                    a[i][1] = __float_as_uint(Ab[(g + 8) * S1 + c]);
                    a[i][2] = __float_as_uint(Ab[g * S1 + c + 4]);
                    a[i][3] = __float_as_uint(Ab[(g + 8) * S1 + c + 4]);
                }
                unsigned bf[2][2];
#pragma unroll
                for (int j = 0; j < 2; j++) {
                    const float* Bb = sW2 + (k0 + c) * S2 + n02 + j * 8 + g;
                    bf[j][0] = __float_as_uint(Bb[0]);
                    bf[j][1] = __float_as_uint(Bb[4 * S2]);
                }
#pragma unroll
                for (int i = 0; i < 2; i++)
#pragma unroll
                    for (int j = 0; j < 2; j++) mma_tf32(acc[i][j], a[i], bf[j]);
            }

#pragma unroll
            for (int i = 0; i < 2; i++)
#pragma unroll
                for (int j = 0; j < 2; j++) {
                    int row = m0 + i * 16 + g;
                    int col = n02 + j * 8 + 2 * c;
                    if (e0 + row < n_edges) {
                        float2 v;
                        v.x = leaky(acc[i][j][0] + sB2[col]);
                        v.y = leaky(acc[i][j][1] + sB2[col + 1]);
                        *reinterpret_cast<float2*>(out + (size_t)(e0 + row) * OD + col) = v;
                    }
                    if (e0 + row + 8 < n_edges) {
                        float2 v;
                        v.x = leaky(acc[i][j][2] + sB2[col]);
                        v.y = leaky(acc[i][j][3] + sB2[col + 1]);
                        *reinterpret_cast<float2*>(out + (size_t)(e0 + row + 8) * OD + col) = v;
                    }
                }
        }
        __syncthreads();   // protect sA1/sA2 reuse across persistent iterations
    }
}

// ---------------------------------------------------------------------------
// Launch. Inputs (metadata order): x, edge_index(int32), W0, b0, W1, b1, W2, b2
// ---------------------------------------------------------------------------
extern "C" void kernel_launch(void* const* d_in, const int* in_sizes, int n_in,
                              void* d_out, int out_size)
{
    const float* x  = (const float*)d_in[0];
    const int*   ei = (const int*)d_in[1];
    const float* W0 = (const float*)d_in[2];
    const float* b0 = (const float*)d_in[3];
    const float* W1 = (const float*)d_in[4];
    const float* b1 = (const float*)d_in[5];
    const float* W2 = (const float*)d_in[6];
    const float* b2 = (const float*)d_in[7];
    float* out = (float*)d_out;

    const int n_nodes = in_sizes[0] / ND;
    const int n_edges = in_sizes[1] / 2;

    cudaFuncSetAttribute(edge_mlp, cudaFuncAttributeMaxDynamicSharedMemorySize, SMEM_BYTES);

    node_gemm<<<(n_nodes + 63) / 64, 256>>>(x, W0, n_nodes);
    edge_mlp<<<148, 256, SMEM_BYTES>>>(ei, W1, W2, b0, b1, b2, out, n_edges, n_nodes);
}

// round 7
// speedup vs baseline: 1.7350x; 1.7350x over previous
#include <cuda_runtime.h>

// ---------------------------------------------------------------------------
// EdgeAttrConstruct: out[e] = L(L(L((x[s]+x[d])@W0+b0)@W1+b1)@W2+b2), L=leaky(0.05)
// Factored: h0 = x@W0 per node;  per edge: act1 = L(h0[s]+h0[d]+b0), then two
// TF32 tensor-core GEMMs per 128-edge tile, weights smem-resident, single
// in-place activation buffer. edge_index is int32 (JAX canonicalization).
// ---------------------------------------------------------------------------

#define SLOPE 0.05f

constexpr int ND = 64;
constexpr int HD = 128;
constexpr int OD = 64;
constexpr int MAX_NODES = 50000;

constexpr int TILE_E = 128;         // edges per tile
constexpr int SA = 132;             // act stride (==4 mod 32: conflict-free A-frag LDS)
constexpr int S1 = 136;             // W1 stride  (==8 mod 32: conflict-free B-frag LDS)
constexpr int S2 = 72;              // W2 stride  (==8 mod 32)
constexpr int NW1 = HD * S1;        // 17408 floats
constexpr int NW2 = HD * S2;        //  9216 floats
constexpr int NACT = TILE_E * SA;   // 16896 floats
constexpr int SMEM_FLOATS = NW1 + NW2 + NACT + 128 + 128 + 64 + 2 * TILE_E;
constexpr int SMEM_BYTES = SMEM_FLOATS * 4;   // ~176 KB

__device__ float g_h0[(size_t)MAX_NODES * HD];

__device__ __forceinline__ float leaky(float v) { return v >= 0.f ? v : SLOPE * v; }

__device__ __forceinline__ unsigned tf32u(float x) {
    unsigned u;
    asm("cvt.rna.tf32.f32 %0, %1;" : "=r"(u) : "f"(x));
    return u;
}
__device__ __forceinline__ float tf32f(float x) { return __uint_as_float(tf32u(x)); }

__device__ __forceinline__ void mma_tf32(float* c, const unsigned* a, const unsigned* b) {
    asm volatile(
        "mma.sync.aligned.m16n8k8.row.col.f32.tf32.tf32.f32 "
        "{%0,%1,%2,%3}, {%4,%5,%6,%7}, {%8,%9}, {%0,%1,%2,%3};"
        : "+f"(c[0]), "+f"(c[1]), "+f"(c[2]), "+f"(c[3])
        : "r"(a[0]), "r"(a[1]), "r"(a[2]), "r"(a[3]), "r"(b[0]), "r"(b[1]));
}

// ---------------------------------------------------------------------------
// Kernel 1: g_h0 = x @ W0   (50000x64 @ 64x128)
// ---------------------------------------------------------------------------
__global__ __launch_bounds__(256) void node_gemm(
    const float* __restrict__ x, const float* __restrict__ W0, int n_nodes)
{
    __shared__ float sW[ND * HD];
    __shared__ float sX[64 * 68];

    const int tid = threadIdx.x;
    for (int i = tid; i < ND * HD; i += 256) sW[i] = W0[i];

    const int node0 = blockIdx.x * 64;
    for (int t = tid; t < 64 * 16; t += 256) {
        int r = t >> 4, q = t & 15;
        int node = node0 + r;
        float4 v = make_float4(0.f, 0.f, 0.f, 0.f);
        if (node < n_nodes) v = *reinterpret_cast<const float4*>(x + (size_t)node * ND + q * 4);
        *reinterpret_cast<float4*>(sX + r * 68 + q * 4) = v;
    }
    __syncthreads();

    const int tx = tid & 31, ty = tid >> 5;
    float acc[8][4];
#pragma unroll
    for (int i = 0; i < 8; i++)
#pragma unroll
        for (int j = 0; j < 4; j++) acc[i][j] = 0.f;

#pragma unroll 4
    for (int k = 0; k < ND; k++) {
        float w[4];
#pragma unroll
        for (int j = 0; j < 4; j++) w[j] = sW[k * HD + tx + 32 * j];
#pragma unroll
        for (int i = 0; i < 8; i++) {
            float xv = sX[(ty + 8 * i) * 68 + k];
#pragma unroll
            for (int j = 0; j < 4; j++) acc[i][j] = fmaf(xv, w[j], acc[i][j]);
        }
    }

#pragma unroll
    for (int i = 0; i < 8; i++) {
        int node = node0 + ty + 8 * i;
        if (node < n_nodes) {
#pragma unroll
            for (int j = 0; j < 4; j++)
                g_h0[(size_t)node * HD + tx + 32 * j] = acc[i][j];
        }
    }
}

// ---------------------------------------------------------------------------
// Kernel 2: persistent edge MLP. grid=148, 512 threads, ~176 KB dyn smem.
// Per 128-edge tile:
//   idx stage: sIdx <- edge_index (2x128 ints, coalesced)
//   gather:    sAct = tf32(leaky(h0[s]+h0[d]+b0))          [128][132]
//   GEMM1:     regs = sAct @ W1 (16 warps, 32x32 tiles); sync;
//              sAct = tf32(leaky(regs + b1))  (in-place overwrite); sync
//   GEMM2:     out  = leaky(sAct @ W2 + b2)  (8 warps, 32x32 tiles) -> gmem
// ---------------------------------------------------------------------------
__global__ __launch_bounds__(512) void edge_mlp(
    const int* __restrict__ ei,
    const float* __restrict__ W1, const float* __restrict__ W2,
    const float* __restrict__ b0, const float* __restrict__ b1,
    const float* __restrict__ b2,
    float* __restrict__ out, int n_edges, int n_nodes)
{
    extern __shared__ float sm[];
    float* sW1 = sm;                 // [128][136] tf32
    float* sW2 = sW1 + NW1;          // [128][72]  tf32
    float* sAct = sW2 + NW2;         // [128][132] act1, then act2 (in place)
    float* sB0 = sAct + NACT;        // [128]
    float* sB1 = sB0 + 128;          // [128]
    float* sB2 = sB1 + 128;          // [64]
    int*   sIdx = (int*)(sB2 + 64);  // [2][128] clamped edge indices

    const int tid = threadIdx.x;

    for (int i = tid; i < HD * HD; i += 512)
        sW1[(i >> 7) * S1 + (i & 127)] = tf32f(W1[i]);
    for (int i = tid; i < HD * OD; i += 512)
        sW2[(i >> 6) * S2 + (i & 63)] = tf32f(W2[i]);
    if (tid < 128) { sB0[tid] = b0[tid]; sB1[tid] = b1[tid]; }
    else if (tid >= 256 && tid < 320) sB2[tid - 256] = b2[tid - 256];
    __syncthreads();

    const int lane = tid & 31, wid = tid >> 5;
    const int g = lane >> 2, c = lane & 3;
    // GEMM1: 16 warps, 4(m) x 4(n) grid of 32x32 tiles
    const int m0 = (wid & 3) * 32;
    const int n0 = (wid >> 2) * 32;

    const int n_tiles = (n_edges + TILE_E - 1) / TILE_E;
    for (int tile = blockIdx.x; tile < n_tiles; tile += gridDim.x) {
        const int e0 = tile * TILE_E;

        // ---- stage indices once (coalesced), clamped ----
        if (tid < 2 * TILE_E) {
            int half = tid >> 7;          // 0 = src, 1 = dst
            int e = tid & (TILE_E - 1);
            int v = 0;
            if (e0 + e < n_edges)
                v = __ldg(ei + (size_t)half * n_edges + e0 + e);
            sIdx[tid] = min(max(v, 0), n_nodes - 1);
        }
        __syncthreads();

        // ---- gather + layer-0 bias/activation ----
        for (int t = tid; t < TILE_E * 32; t += 512) {
            int e = t >> 5, q = t & 31;
            float4 w;
            if (e0 + e < n_edges) {
                int s = sIdx[e];
                int d = sIdx[TILE_E + e];
                float4 va = *reinterpret_cast<const float4*>(&g_h0[(size_t)s * HD + q * 4]);
                float4 vb = *reinterpret_cast<const float4*>(&g_h0[(size_t)d * HD + q * 4]);
                float4 bb = *reinterpret_cast<const float4*>(sB0 + q * 4);
                w.x = tf32f(leaky(va.x + vb.x + bb.x));
                w.y = tf32f(leaky(va.y + vb.y + bb.y));
                w.z = tf32f(leaky(va.z + vb.z + bb.z));
                w.w = tf32f(leaky(va.w + vb.w + bb.w));
            } else {
                w = make_float4(0.f, 0.f, 0.f, 0.f);
            }
            *reinterpret_cast<float4*>(sAct + e * SA + q * 4) = w;
        }
        __syncthreads();

        // ---- GEMM1 mainloop: acc = sAct @ W1 (accumulators stay in regs)
        float acc[2][4][4];
#pragma unroll
        for (int i = 0; i < 2; i++)
#pragma unroll
            for (int j = 0; j < 4; j++)
#pragma unroll
                for (int r = 0; r < 4; r++) acc[i][j][r] = 0.f;

#pragma unroll
        for (int k0 = 0; k0 < HD; k0 += 8) {
            unsigned a[2][4];
#pragma unroll
            for (int i = 0; i < 2; i++) {
                const float* Ab = sAct + (m0 + i * 16) * SA + k0;
                a[i][0] = __float_as_uint(Ab[g * SA + c]);
                a[i][1] = __float_as_uint(Ab[(g + 8) * SA + c]);
                a[i][2] = __float_as_uint(Ab[g * SA + c + 4]);
                a[i][3] = __float_as_uint(Ab[(g + 8) * SA + c + 4]);
            }
            unsigned bf[4][2];
#pragma unroll
            for (int j = 0; j < 4; j++) {
                const float* Bb = sW1 + (k0 + c) * S1 + n0 + j * 8 + g;
                bf[j][0] = __float_as_uint(Bb[0]);
                bf[j][1] = __float_as_uint(Bb[4 * S1]);
            }
#pragma unroll
            for (int i = 0; i < 2; i++)
#pragma unroll
                for (int j = 0; j < 4; j++) mma_tf32(acc[i][j], a[i], bf[j]);
        }
        __syncthreads();   // everyone done READING sAct before in-place overwrite

        // ---- layer-1 epilogue: write act2 into sAct (in place)
#pragma unroll
        for (int i = 0; i < 2; i++)
#pragma unroll
            for (int j = 0; j < 4; j++) {
                int row = m0 + i * 16 + g;
                int col = n0 + j * 8 + 2 * c;
                float2 v0, v1;
                v0.x = tf32f(leaky(acc[i][j][0] + sB1[col]));
                v0.y = tf32f(leaky(acc[i][j][1] + sB1[col + 1]));
                v1.x = tf32f(leaky(acc[i][j][2] + sB1[col]));
                v1.y = tf32f(leaky(acc[i][j][3] + sB1[col + 1]));
                *reinterpret_cast<float2*>(sAct + row * SA + col) = v0;
                *reinterpret_cast<float2*>(sAct + (row + 8) * SA + col) = v1;
            }
        __syncthreads();

        // ---- GEMM2 (8 warps, 4(m) x 2(n) grid of 32x32 tiles) -> gmem
        if (wid < 8) {
            const int n02 = (wid >> 2) * 32;   // 0 or 32
            float acc2[2][4][4];
#pragma unroll
            for (int i = 0; i < 2; i++)
#pragma unroll
                for (int j = 0; j < 4; j++)
#pragma unroll
                    for (int r = 0; r < 4; r++) acc2[i][j][r] = 0.f;

#pragma unroll
            for (int k0 = 0; k0 < HD; k0 += 8) {
                unsigned a[2][4];
#pragma unroll
                for (int i = 0; i < 2; i++) {
                    const float* Ab = sAct + (m0 + i * 16) * SA + k0;
                    a[i][0] = __float_as_uint(Ab[g * SA + c]);
                    a[i][1] = __float_as_uint(Ab[(g + 8) * SA + c]);
                    a[i][2] = __float_as_uint(Ab[g * SA + c + 4]);
                    a[i][3] = __float_as_uint(Ab[(g + 8) * SA + c + 4]);
                }
                unsigned bf[4][2];
#pragma unroll
                for (int j = 0; j < 4; j++) {
                    const float* Bb = sW2 + (k0 + c) * S2 + n02 + j * 8 + g;
                    bf[j][0] = __float_as_uint(Bb[0]);
                    bf[j][1] = __float_as_uint(Bb[4 * S2]);
                }
#pragma unroll
                for (int i = 0; i < 2; i++)
#pragma unroll
                    for (int j = 0; j < 4; j++) mma_tf32(acc2[i][j], a[i], bf[j]);
            }

#pragma unroll
            for (int i = 0; i < 2; i++)
#pragma unroll
                for (int j = 0; j < 4; j++) {
                    int row = m0 + i * 16 + g;
                    int col = n02 + j * 8 + 2 * c;
                    if (e0 + row < n_edges) {
                        float2 v;
                        v.x = leaky(acc2[i][j][0] + sB2[col]);
                        v.y = leaky(acc2[i][j][1] + sB2[col + 1]);
                        *reinterpret_cast<float2*>(out + (size_t)(e0 + row) * OD + col) = v;
                    }
                    if (e0 + row + 8 < n_edges) {
                        float2 v;
                        v.x = leaky(acc2[i][j][2] + sB2[col]);
                        v.y = leaky(acc2[i][j][3] + sB2[col + 1]);
                        *reinterpret_cast<float2*>(out + (size_t)(e0 + row + 8) * OD + col) = v;
                    }
                }
        }
        __syncthreads();   // sAct/sIdx reads done before next tile
    }
}

// ---------------------------------------------------------------------------
// Launch. Inputs: x, edge_index(int32), W0, b0, W1, b1, W2, b2
// ---------------------------------------------------------------------------
extern "C" void kernel_launch(void* const* d_in, const int* in_sizes, int n_in,
                              void* d_out, int out_size)
{
    const float* x  = (const float*)d_in[0];
    const int*   ei = (const int*)d_in[1];
    const float* W0 = (const float*)d_in[2];
    const float* b0 = (const float*)d_in[3];
    const float* W1 = (const float*)d_in[4];
    const float* b1 = (const float*)d_in[5];
    const float* W2 = (const float*)d_in[6];
    const float* b2 = (const float*)d_in[7];
    float* out = (float*)d_out;

    const int n_nodes = in_sizes[0] / ND;
    const int n_edges = in_sizes[1] / 2;

    cudaFuncSetAttribute(edge_mlp, cudaFuncAttributeMaxDynamicSharedMemorySize, SMEM_BYTES);

    node_gemm<<<(n_nodes + 63) / 64, 256>>>(x, W0, n_nodes);
    edge_mlp<<<148, 512, SMEM_BYTES>>>(ei, W1, W2, b0, b1, b2, out, n_edges, n_nodes);
}

// round 8
// speedup vs baseline: 1.7396x; 1.0026x over previous
#include <cuda_runtime.h>

// ---------------------------------------------------------------------------
// EdgeAttrConstruct: out[e] = L(L(L((x[s]+x[d])@W0+b0)@W1+b1)@W2+b2), L=leaky(0.05)
// Factored: h0 = x@W0 per node;  per edge: act1 = L(h0[s]+h0[d]+b0), then two
// TF32 tensor-core GEMMs per 128-edge tile. The CTA is split into FOUR
// independent 32-row "band" pipelines (4 warps each) synchronized only by
// named barriers -> no block-wide serialization inside the tile loop.
// edge_index is int32 (JAX canonicalization).
// ---------------------------------------------------------------------------

#define SLOPE 0.05f

constexpr int ND = 64;
constexpr int HD = 128;
constexpr int OD = 64;

constexpr int TILE_E = 128;         // edges per tile (32 per band)
constexpr int SA = 132;             // act stride (==4 mod 32: conflict-free A-frag LDS)
constexpr int S1 = 136;             // W1 stride  (==8 mod 32: conflict-free B-frag LDS)
constexpr int S2 = 72;              // W2 stride  (==8 mod 32)
constexpr int NW1 = HD * S1;        // 17408 floats
constexpr int NW2 = HD * S2;        //  9216 floats
constexpr int NACT = TILE_E * SA;   // 16896 floats
constexpr int SMEM_FLOATS = NW1 + NW2 + NACT + 128 + 128 + 64;
constexpr int SMEM_BYTES = SMEM_FLOATS * 4;   // 175360 B

__device__ float g_h0[(size_t)50000 * HD];

__device__ __forceinline__ float leaky(float v) { return v >= 0.f ? v : SLOPE * v; }

__device__ __forceinline__ unsigned tf32u(float x) {
    unsigned u;
    asm("cvt.rna.tf32.f32 %0, %1;" : "=r"(u) : "f"(x));
    return u;
}
__device__ __forceinline__ float tf32f(float x) { return __uint_as_float(tf32u(x)); }

__device__ __forceinline__ void mma_tf32(float* c, const unsigned* a, const unsigned* b) {
    asm volatile(
        "mma.sync.aligned.m16n8k8.row.col.f32.tf32.tf32.f32 "
        "{%0,%1,%2,%3}, {%4,%5,%6,%7}, {%8,%9}, {%0,%1,%2,%3};"
        : "+f"(c[0]), "+f"(c[1]), "+f"(c[2]), "+f"(c[3])
        : "r"(a[0]), "r"(a[1]), "r"(a[2]), "r"(a[3]), "r"(b[0]), "r"(b[1]));
}

__device__ __forceinline__ void band_bar(int band) {
    asm volatile("bar.sync %0, 128;" :: "r"(band + 1) : "memory");
}

// ---------------------------------------------------------------------------
// Kernel 1: g_h0 = x @ W0   (50000x64 @ 64x128)
// ---------------------------------------------------------------------------
__global__ __launch_bounds__(256) void node_gemm(
    const float* __restrict__ x, const float* __restrict__ W0, int n_nodes)
{
    __shared__ float sW[ND * HD];
    __shared__ float sX[64 * 68];

    const int tid = threadIdx.x;
    for (int i = tid; i < ND * HD; i += 256) sW[i] = W0[i];

    const int node0 = blockIdx.x * 64;
    for (int t = tid; t < 64 * 16; t += 256) {
        int r = t >> 4, q = t & 15;
        int node = node0 + r;
        float4 v = make_float4(0.f, 0.f, 0.f, 0.f);
        if (node < n_nodes) v = *reinterpret_cast<const float4*>(x + (size_t)node * ND + q * 4);
        *reinterpret_cast<float4*>(sX + r * 68 + q * 4) = v;
    }
    __syncthreads();

    const int tx = tid & 31, ty = tid >> 5;
    float acc[8][4];
#pragma unroll
    for (int i = 0; i < 8; i++)
#pragma unroll
        for (int j = 0; j < 4; j++) acc[i][j] = 0.f;

#pragma unroll 4
    for (int k = 0; k < ND; k++) {
        float w[4];
#pragma unroll
        for (int j = 0; j < 4; j++) w[j] = sW[k * HD + tx + 32 * j];
#pragma unroll
        for (int i = 0; i < 8; i++) {
            float xv = sX[(ty + 8 * i) * 68 + k];
#pragma unroll
            for (int j = 0; j < 4; j++) acc[i][j] = fmaf(xv, w[j], acc[i][j]);
        }
    }

#pragma unroll
    for (int i = 0; i < 8; i++) {
        int node = node0 + ty + 8 * i;
        if (node < n_nodes) {
#pragma unroll
            for (int j = 0; j < 4; j++)
                g_h0[(size_t)node * HD + tx + 32 * j] = acc[i][j];
        }
    }
}

// ---------------------------------------------------------------------------
// Kernel 2: persistent edge MLP. grid=148, 512 threads, 175 KB dyn smem.
// 4 bands x 4 warps. Per 128-edge tile, each band independently:
//   gather:  its 32 rows of sAct = tf32(leaky(h0[s]+h0[d]+b0))
//   GEMM1:   band rows @ W1 -> regs; epilogue overwrites band rows in place
//   GEMM2:   band rows @ W2 -> gmem (all 4 warps, 32x16 tiles)
// synchronized only with bar.sync(band+1, 128).
// ---------------------------------------------------------------------------
__global__ __launch_bounds__(512) void edge_mlp(
    const int* __restrict__ ei,
    const float* __restrict__ W1, const float* __restrict__ W2,
    const float* __restrict__ b0, const float* __restrict__ b1,
    const float* __restrict__ b2,
    float* __restrict__ out, int n_edges, int n_nodes)
{
    extern __shared__ float sm[];
    float* sW1 = sm;                 // [128][136] tf32
    float* sW2 = sW1 + NW1;          // [128][72]  tf32
    float* sAct = sW2 + NW2;         // [128][132]
    float* sB0 = sAct + NACT;        // [128]
    float* sB1 = sB0 + 128;          // [128]
    float* sB2 = sB1 + 128;          // [64]

    const int tid = threadIdx.x;

    for (int i = tid; i < HD * HD; i += 512)
        sW1[(i >> 7) * S1 + (i & 127)] = tf32f(W1[i]);
    for (int i = tid; i < HD * OD; i += 512)
        sW2[(i >> 6) * S2 + (i & 63)] = tf32f(W2[i]);
    if (tid < 128) { sB0[tid] = b0[tid]; sB1[tid] = b1[tid]; }
    else if (tid >= 256 && tid < 320) sB2[tid - 256] = b2[tid - 256];
    __syncthreads();

    const int lane = tid & 31, wid = tid >> 5;
    const int g = lane >> 2, c = lane & 3;
    const int band = wid & 3;        // 0..3 : 32-row band, 4 warps each
    const int sub  = wid >> 2;       // 0..3 : position within band
    const int m0  = band * 32;       // GEMM m-tile base (== sAct row base)
    const int n0  = sub * 32;        // GEMM1 n-tile base
    const int n02 = sub * 16;        // GEMM2 n-tile base

    const int n_tiles = (n_edges + TILE_E - 1) / TILE_E;
    for (int tile = blockIdx.x; tile < n_tiles; tile += gridDim.x) {
        const int e0 = tile * TILE_E;

        // ---- gather: this warp owns 8 rows [m0+sub*8, +8) of the band ----
        {
            const int e_base = e0 + m0 + sub * 8;
            // lanes 0-7 load src idx for rows 0..7, lanes 8-15 load dst idx
            int idx = 0;
            if (lane < 16) {
                int e = e_base + (lane & 7);
                if (e < n_edges)
                    idx = __ldg(ei + (lane < 8 ? 0 : (size_t)n_edges) + e);
            }
            idx = min(max(idx, 0), n_nodes - 1);
            float4 bb = *reinterpret_cast<const float4*>(sB0 + lane * 4);
#pragma unroll
            for (int i = 0; i < 8; i++) {
                int s = __shfl_sync(0xffffffffu, idx, i);
                int d = __shfl_sync(0xffffffffu, idx, i + 8);
                float4 w;
                if (e_base + i < n_edges) {
                    float4 va = *reinterpret_cast<const float4*>(&g_h0[(size_t)s * HD + lane * 4]);
                    float4 vb = *reinterpret_cast<const float4*>(&g_h0[(size_t)d * HD + lane * 4]);
                    w.x = tf32f(leaky(va.x + vb.x + bb.x));
                    w.y = tf32f(leaky(va.y + vb.y + bb.y));
                    w.z = tf32f(leaky(va.z + vb.z + bb.z));
                    w.w = tf32f(leaky(va.w + vb.w + bb.w));
                } else {
                    w = make_float4(0.f, 0.f, 0.f, 0.f);
                }
                *reinterpret_cast<float4*>(sAct + (m0 + sub * 8 + i) * SA + lane * 4) = w;
            }
        }
        band_bar(band);

        // ---- GEMM1 mainloop: acc = sAct[band] @ W1 ----
        float acc[2][4][4];
#pragma unroll
        for (int i = 0; i < 2; i++)
#pragma unroll
            for (int j = 0; j < 4; j++)
#pragma unroll
                for (int r = 0; r < 4; r++) acc[i][j][r] = 0.f;

#pragma unroll
        for (int k0 = 0; k0 < HD; k0 += 8) {
            unsigned a[2][4];
#pragma unroll
            for (int i = 0; i < 2; i++) {
                const float* Ab = sAct + (m0 + i * 16) * SA + k0;
                a[i][0] = __float_as_uint(Ab[g * SA + c]);
                a[i][1] = __float_as_uint(Ab[(g + 8) * SA + c]);
                a[i][2] = __float_as_uint(Ab[g * SA + c + 4]);
                a[i][3] = __float_as_uint(Ab[(g + 8) * SA + c + 4]);
            }
            unsigned bf[4][2];
#pragma unroll
            for (int j = 0; j < 4; j++) {
                const float* Bb = sW1 + (k0 + c) * S1 + n0 + j * 8 + g;
                bf[j][0] = __float_as_uint(Bb[0]);
                bf[j][1] = __float_as_uint(Bb[4 * S1]);
            }
#pragma unroll
            for (int i = 0; i < 2; i++)
#pragma unroll
                for (int j = 0; j < 4; j++) mma_tf32(acc[i][j], a[i], bf[j]);
        }
        band_bar(band);    // band done READING its sAct rows

        // ---- layer-1 epilogue: overwrite band rows in place ----
#pragma unroll
        for (int i = 0; i < 2; i++)
#pragma unroll
            for (int j = 0; j < 4; j++) {
                int row = m0 + i * 16 + g;
                int col = n0 + j * 8 + 2 * c;
                float2 v0, v1;
                v0.x = tf32f(leaky(acc[i][j][0] + sB1[col]));
                v0.y = tf32f(leaky(acc[i][j][1] + sB1[col + 1]));
                v1.x = tf32f(leaky(acc[i][j][2] + sB1[col]));
                v1.y = tf32f(leaky(acc[i][j][3] + sB1[col + 1]));
                *reinterpret_cast<float2*>(sAct + row * SA + col) = v0;
                *reinterpret_cast<float2*>(sAct + (row + 8) * SA + col) = v1;
            }
        band_bar(band);

        // ---- GEMM2: out[band] = leaky(sAct[band] @ W2 + b2), 32x16 tiles ----
        {
            float acc2[2][2][4];
#pragma unroll
            for (int i = 0; i < 2; i++)
#pragma unroll
                for (int j = 0; j < 2; j++)
#pragma unroll
                    for (int r = 0; r < 4; r++) acc2[i][j][r] = 0.f;

#pragma unroll
            for (int k0 = 0; k0 < HD; k0 += 8) {
                unsigned a[2][4];
#pragma unroll
                for (int i = 0; i < 2; i++) {
                    const float* Ab = sAct + (m0 + i * 16) * SA + k0;
                    a[i][0] = __float_as_uint(Ab[g * SA + c]);
                    a[i][1] = __float_as_uint(Ab[(g + 8) * SA + c]);
                    a[i][2] = __float_as_uint(Ab[g * SA + c + 4]);
                    a[i][3] = __float_as_uint(Ab[(g + 8) * SA + c + 4]);
                }
                unsigned bf[2][2];
#pragma unroll
                for (int j = 0; j < 2; j++) {
                    const float* Bb = sW2 + (k0 + c) * S2 + n02 + j * 8 + g;
                    bf[j][0] = __float_as_uint(Bb[0]);
                    bf[j][1] = __float_as_uint(Bb[4 * S2]);
                }
#pragma unroll
                for (int i = 0; i < 2; i++)
#pragma unroll
                    for (int j = 0; j < 2; j++) mma_tf32(acc2[i][j], a[i], bf[j]);
            }

#pragma unroll
            for (int i = 0; i < 2; i++)
#pragma unroll
                for (int j = 0; j < 2; j++) {
                    int row = m0 + i * 16 + g;
                    int col = n02 + j * 8 + 2 * c;
                    if (e0 + row < n_edges) {
                        float2 v;
                        v.x = leaky(acc2[i][j][0] + sB2[col]);
                        v.y = leaky(acc2[i][j][1] + sB2[col + 1]);
                        *reinterpret_cast<float2*>(out + (size_t)(e0 + row) * OD + col) = v;
                    }
                    if (e0 + row + 8 < n_edges) {
                        float2 v;
                        v.x = leaky(acc2[i][j][2] + sB2[col]);
                        v.y = leaky(acc2[i][j][3] + sB2[col + 1]);
                        *reinterpret_cast<float2*>(out + (size_t)(e0 + row + 8) * OD + col) = v;
                    }
                }
        }
        band_bar(band);    // band's sAct reads done before next tile's gather
    }
}

// ---------------------------------------------------------------------------
// Launch. Inputs: x, edge_index(int32), W0, b0, W1, b1, W2, b2
// ---------------------------------------------------------------------------
extern "C" void kernel_launch(void* const* d_in, const int* in_sizes, int n_in,
                              void* d_out, int out_size)
{
    const float* x  = (const float*)d_in[0];
    const int*   ei = (const int*)d_in[1];
    const float* W0 = (const float*)d_in[2];
    const float* b0 = (const float*)d_in[3];
    const float* W1 = (const float*)d_in[4];
    const float* b1 = (const float*)d_in[5];
    const float* W2 = (const float*)d_in[6];
    const float* b2 = (const float*)d_in[7];
    float* out = (float*)d_out;

    const int n_nodes = in_sizes[0] / ND;
    const int n_edges = in_sizes[1] / 2;

    cudaFuncSetAttribute(edge_mlp, cudaFuncAttributeMaxDynamicSharedMemorySize, SMEM_BYTES);

    node_gemm<<<(n_nodes + 63) / 64, 256>>>(x, W0, n_nodes);
    edge_mlp<<<148, 512, SMEM_BYTES>>>(ei, W1, W2, b0, b1, b2, out, n_edges, n_nodes);
}